// round 1
// baseline (speedup 1.0000x reference)
#include <cuda_runtime.h>
#include <math.h>

// Problem constants
constexpr int Bb  = 2;
constexpr int Ss  = 2048;
constexpr int Ee  = 2048;
constexpr int Hh  = 32;
constexpr int HKVv= 8;
constexpr int Dd  = 64;
constexpr int MS  = Bb * Ss;      // 4096 rows

// Scratch (no cudaMalloc allowed)
__device__ float g_q[MS * Hh * Dd];       // (b,s,h,d) row-major = (M, 2048)
__device__ float g_k[MS * HKVv * Dd];     // (M, 512)
__device__ float g_v[MS * HKVv * Dd];
__device__ float g_attn[MS * Hh * Dd];

// ---------------------------------------------------------------------------
// NT SGEMM: C[M,N] = A[M,K] * W[N,K]^T.  Tiles 128x128x8, 256 thr, 8x8 micro.
// ---------------------------------------------------------------------------
__global__ void __launch_bounds__(256, 2) gemm_nt_kernel(
    const float* __restrict__ A, const float* __restrict__ W,
    float* __restrict__ C, int K, int ldc)
{
    __shared__ float As[2][8][132];
    __shared__ float Bs[2][8][132];

    const int tid = threadIdx.x;
    const int tx  = tid & 15;     // n direction
    const int ty  = tid >> 4;     // m direction
    const int m0  = blockIdx.y * 128;
    const int n0  = blockIdx.x * 128;
    const int lrow = tid >> 1;          // 0..127
    const int lk4  = (tid & 1) << 2;    // 0 or 4

    const float* Ap = A + (size_t)(m0 + lrow) * K + lk4;
    const float* Wp = W + (size_t)(n0 + lrow) * K + lk4;

    float acc[8][8];
#pragma unroll
    for (int i = 0; i < 8; ++i)
#pragma unroll
        for (int j = 0; j < 8; ++j) acc[i][j] = 0.f;

    // prologue: tile 0
    float4 av = *(const float4*)Ap;
    float4 bv = *(const float4*)Wp;
    As[0][lk4 + 0][lrow] = av.x; As[0][lk4 + 1][lrow] = av.y;
    As[0][lk4 + 2][lrow] = av.z; As[0][lk4 + 3][lrow] = av.w;
    Bs[0][lk4 + 0][lrow] = bv.x; Bs[0][lk4 + 1][lrow] = bv.y;
    Bs[0][lk4 + 2][lrow] = bv.z; Bs[0][lk4 + 3][lrow] = bv.w;
    __syncthreads();

    const int nt = K >> 3;
    int buf = 0;
    for (int t = 0; t < nt; ++t) {
        float4 av2, bv2;
        if (t + 1 < nt) {
            av2 = *(const float4*)(Ap + (size_t)(t + 1) * 8);
            bv2 = *(const float4*)(Wp + (size_t)(t + 1) * 8);
        }
#pragma unroll
        for (int kk = 0; kk < 8; ++kk) {
            float4 a0 = *(const float4*)&As[buf][kk][4 * ty];
            float4 a1 = *(const float4*)&As[buf][kk][64 + 4 * ty];
            float4 b0 = *(const float4*)&Bs[buf][kk][4 * tx];
            float4 b1 = *(const float4*)&Bs[buf][kk][64 + 4 * tx];
            float aa[8] = {a0.x, a0.y, a0.z, a0.w, a1.x, a1.y, a1.z, a1.w};
            float bb[8] = {b0.x, b0.y, b0.z, b0.w, b1.x, b1.y, b1.z, b1.w};
#pragma unroll
            for (int i = 0; i < 8; ++i)
#pragma unroll
                for (int j = 0; j < 8; ++j)
                    acc[i][j] += aa[i] * bb[j];
        }
        if (t + 1 < nt) {
            buf ^= 1;
            As[buf][lk4 + 0][lrow] = av2.x; As[buf][lk4 + 1][lrow] = av2.y;
            As[buf][lk4 + 2][lrow] = av2.z; As[buf][lk4 + 3][lrow] = av2.w;
            Bs[buf][lk4 + 0][lrow] = bv2.x; Bs[buf][lk4 + 1][lrow] = bv2.y;
            Bs[buf][lk4 + 2][lrow] = bv2.z; Bs[buf][lk4 + 3][lrow] = bv2.w;
            __syncthreads();
        }
    }

#pragma unroll
    for (int i = 0; i < 8; ++i) {
        int m = m0 + ((i < 4) ? (4 * ty + i) : (64 + 4 * ty + (i - 4)));
        float* cp = C + (size_t)m * ldc + n0;
        *(float4*)(cp + 4 * tx)      = make_float4(acc[i][0], acc[i][1], acc[i][2], acc[i][3]);
        *(float4*)(cp + 64 + 4 * tx) = make_float4(acc[i][4], acc[i][5], acc[i][6], acc[i][7]);
    }
}

// ---------------------------------------------------------------------------
// RoPE applied in-place to q (B,S,H,D) and k (B,S,HKV,D)
// ---------------------------------------------------------------------------
__global__ void rope_kernel(float* __restrict__ q, float* __restrict__ k,
                            const float* __restrict__ cosb, const float* __restrict__ sinb)
{
    const int NQ = MS * Hh * 32;
    const int NK = MS * HKVv * 32;
    int idx = blockIdx.x * blockDim.x + threadIdx.x;
    if (idx < NQ) {
        int d = idx & 31;
        int t = idx >> 5;               // (b*S+s)*H + h
        int bs = t / Hh;
        int s = bs & (Ss - 1);
        float c1 = cosb[s * Dd + d],      s1 = sinb[s * Dd + d];
        float c2 = cosb[s * Dd + d + 32], s2 = sinb[s * Dd + d + 32];
        float* p = q + (size_t)t * Dd;
        float x1 = p[d], x2 = p[d + 32];
        p[d]      = x1 * c1 - x2 * s1;
        p[d + 32] = x2 * c2 + x1 * s2;
    } else if (idx < NQ + NK) {
        int j = idx - NQ;
        int d = j & 31;
        int t = j >> 5;                 // (b*S+s)*HKV + h
        int bs = t / HKVv;
        int s = bs & (Ss - 1);
        float c1 = cosb[s * Dd + d],      s1 = sinb[s * Dd + d];
        float c2 = cosb[s * Dd + d + 32], s2 = sinb[s * Dd + d + 32];
        float* p = k + (size_t)t * Dd;
        float x1 = p[d], x2 = p[d + 32];
        p[d]      = x1 * c1 - x2 * s1;
        p[d + 32] = x2 * c2 + x1 * s2;
    }
}

// ---------------------------------------------------------------------------
// Flash attention, fp32. Q tile 128, KV tile 64, 128 threads, 8x8 micro-tiles.
// grid = (S/128, H, B)
// ---------------------------------------------------------------------------
constexpr int QT   = 128;
constexpr int KT   = 64;
constexpr int QT_P = QT + 4;   // 132
constexpr int KT_P = KT + 4;   // 68

constexpr int OFF_QT = 0;                      // Qt[64][QT_P]  (d-major)
constexpr int OFF_KT = OFF_QT + 64 * QT_P;     // Kt[64][KT_P]  (d-major)
constexpr int OFF_VS = OFF_KT + 64 * KT_P;     // Vs[KT][64]    (natural)
constexpr int OFF_PT = OFF_VS + KT * 64;       // Pt[KT][QT_P]  (kv-major)
constexpr int SMEM_FLOATS = OFF_PT + KT * QT_P;
constexpr int SMEM_BYTES  = SMEM_FLOATS * 4;   // ~101 KB

__global__ void __launch_bounds__(128, 2) attn_kernel(
    const float* __restrict__ q, const float* __restrict__ k,
    const float* __restrict__ v, float* __restrict__ o_out)
{
    extern __shared__ float sm[];
    float* Qt = sm + OFF_QT;
    float* Kt = sm + OFF_KT;
    float* Vs = sm + OFF_VS;
    float* Pt = sm + OFF_PT;

    const int tid = threadIdx.x;
    const int tn  = tid & 7;     // kv / d-col direction (low lane bits -> shfl reduce)
    const int tm  = tid >> 3;    // 0..15, m direction
    const int q0  = blockIdx.x * QT;
    const int h   = blockIdx.y;
    const int b   = blockIdx.z;
    const int hkv = h >> 2;      // G=4

    const float* qbase = q + ((size_t)(b * Ss) * Hh + h) * Dd;
    const float* kbase = k + ((size_t)(b * Ss) * HKVv + hkv) * Dd;
    const float* vbase = v + ((size_t)(b * Ss) * HKVv + hkv) * Dd;

    // Load Q tile transposed: Qt[d][m]
#pragma unroll
    for (int r = 0; r < 16; ++r) {
        int idx = r * 128 + tid;
        int m  = idx >> 4;
        int d4 = (idx & 15) << 2;
        float4 val = *(const float4*)(qbase + (size_t)(q0 + m) * (Hh * Dd) + d4);
        Qt[(d4 + 0) * QT_P + m] = val.x;
        Qt[(d4 + 1) * QT_P + m] = val.y;
        Qt[(d4 + 2) * QT_P + m] = val.z;
        Qt[(d4 + 3) * QT_P + m] = val.w;
    }

    float o[8][8];
#pragma unroll
    for (int i = 0; i < 8; ++i)
#pragma unroll
        for (int j = 0; j < 8; ++j) o[i][j] = 0.f;
    float mstat[8], lstat[8];
#pragma unroll
    for (int i = 0; i < 8; ++i) { mstat[i] = -1e30f; lstat[i] = 0.f; }

    __syncthreads();

    for (int t = 0; t < Ss / KT; ++t) {
        const int kv0 = t * KT;
        // Load K (transposed) and V (natural)
#pragma unroll
        for (int r = 0; r < 8; ++r) {
            int idx = r * 128 + tid;
            int pos = idx >> 4;
            int d4  = (idx & 15) << 2;
            float4 kval = *(const float4*)(kbase + (size_t)(kv0 + pos) * (HKVv * Dd) + d4);
            Kt[(d4 + 0) * KT_P + pos] = kval.x;
            Kt[(d4 + 1) * KT_P + pos] = kval.y;
            Kt[(d4 + 2) * KT_P + pos] = kval.z;
            Kt[(d4 + 3) * KT_P + pos] = kval.w;
            float4 vval = *(const float4*)(vbase + (size_t)(kv0 + pos) * (HKVv * Dd) + d4);
            *(float4*)(Vs + pos * 64 + d4) = vval;
        }
        __syncthreads();

        // S = Q K^T (raw)
        float s[8][8];
#pragma unroll
        for (int i = 0; i < 8; ++i)
#pragma unroll
            for (int j = 0; j < 8; ++j) s[i][j] = 0.f;

#pragma unroll 8
        for (int d = 0; d < 64; ++d) {
            float4 q0v = *(const float4*)(Qt + d * QT_P + 4 * tm);
            float4 q1v = *(const float4*)(Qt + d * QT_P + 64 + 4 * tm);
            float4 k0v = *(const float4*)(Kt + d * KT_P + 4 * tn);
            float4 k1v = *(const float4*)(Kt + d * KT_P + 32 + 4 * tn);
            float qa[8] = {q0v.x, q0v.y, q0v.z, q0v.w, q1v.x, q1v.y, q1v.z, q1v.w};
            float ka[8] = {k0v.x, k0v.y, k0v.z, k0v.w, k1v.x, k1v.y, k1v.z, k1v.w};
#pragma unroll
            for (int i = 0; i < 8; ++i)
#pragma unroll
                for (int j = 0; j < 8; ++j)
                    s[i][j] += qa[i] * ka[j];
        }

        // online softmax update (scale = 1/sqrt(64) = 0.125)
#pragma unroll
        for (int i = 0; i < 8; ++i) {
#pragma unroll
            for (int j = 0; j < 8; ++j) s[i][j] *= 0.125f;
            float rmax = s[i][0];
#pragma unroll
            for (int j = 1; j < 8; ++j) rmax = fmaxf(rmax, s[i][j]);
            rmax = fmaxf(rmax, __shfl_xor_sync(0xffffffffu, rmax, 1));
            rmax = fmaxf(rmax, __shfl_xor_sync(0xffffffffu, rmax, 2));
            rmax = fmaxf(rmax, __shfl_xor_sync(0xffffffffu, rmax, 4));
            float mnew = fmaxf(mstat[i], rmax);
            float corr = __expf(mstat[i] - mnew);
            float rsum = 0.f;
#pragma unroll
            for (int j = 0; j < 8; ++j) {
                s[i][j] = __expf(s[i][j] - mnew);
                rsum += s[i][j];
            }
            rsum += __shfl_xor_sync(0xffffffffu, rsum, 1);
            rsum += __shfl_xor_sync(0xffffffffu, rsum, 2);
            rsum += __shfl_xor_sync(0xffffffffu, rsum, 4);
            lstat[i] = lstat[i] * corr + rsum;
            mstat[i] = mnew;
#pragma unroll
            for (int j = 0; j < 8; ++j) o[i][j] *= corr;
        }

        // write P transposed: Pt[kv][m]
#pragma unroll
        for (int j = 0; j < 8; ++j) {
            int ncol = (j < 4) ? (4 * tn + j) : (32 + 4 * tn + (j - 4));
            *(float4*)(Pt + ncol * QT_P + 4 * tm)      = make_float4(s[0][j], s[1][j], s[2][j], s[3][j]);
            *(float4*)(Pt + ncol * QT_P + 64 + 4 * tm) = make_float4(s[4][j], s[5][j], s[6][j], s[7][j]);
        }
        __syncthreads();

        // O += P V
#pragma unroll 8
        for (int kv = 0; kv < KT; ++kv) {
            float4 p0 = *(const float4*)(Pt + kv * QT_P + 4 * tm);
            float4 p1 = *(const float4*)(Pt + kv * QT_P + 64 + 4 * tm);
            float4 v0 = *(const float4*)(Vs + kv * 64 + 4 * tn);
            float4 v1 = *(const float4*)(Vs + kv * 64 + 32 + 4 * tn);
            float pa[8] = {p0.x, p0.y, p0.z, p0.w, p1.x, p1.y, p1.z, p1.w};
            float va[8] = {v0.x, v0.y, v0.z, v0.w, v1.x, v1.y, v1.z, v1.w};
#pragma unroll
            for (int i = 0; i < 8; ++i)
#pragma unroll
                for (int j = 0; j < 8; ++j)
                    o[i][j] += pa[i] * va[j];
        }
        __syncthreads();
    }

    // epilogue
    float* obase = o_out + ((size_t)(b * Ss) * Hh + h) * Dd;
#pragma unroll
    for (int i = 0; i < 8; ++i) {
        int m = (i < 4) ? (4 * tm + i) : (64 + 4 * tm + (i - 4));
        float inv = 1.f / lstat[i];
        float* op = obase + (size_t)(q0 + m) * (Hh * Dd);
        *(float4*)(op + 4 * tn)      = make_float4(o[i][0] * inv, o[i][1] * inv, o[i][2] * inv, o[i][3] * inv);
        *(float4*)(op + 32 + 4 * tn) = make_float4(o[i][4] * inv, o[i][5] * inv, o[i][6] * inv, o[i][7] * inv);
    }
}

// ---------------------------------------------------------------------------
extern "C" void kernel_launch(void* const* d_in, const int* in_sizes, int n_in,
                              void* d_out, int out_size)
{
    (void)in_sizes; (void)n_in; (void)out_size;
    const float* x    = (const float*)d_in[0];
    const float* cosb = (const float*)d_in[1];
    const float* sinb = (const float*)d_in[2];
    const float* Wq   = (const float*)d_in[3];
    const float* Wk   = (const float*)d_in[4];
    const float* Wv   = (const float*)d_in[5];
    const float* Wo   = (const float*)d_in[6];
    float* out = (float*)d_out;

    float *qb, *kb, *vb, *ab;
    cudaGetSymbolAddress((void**)&qb, g_q);
    cudaGetSymbolAddress((void**)&kb, g_k);
    cudaGetSymbolAddress((void**)&vb, g_v);
    cudaGetSymbolAddress((void**)&ab, g_attn);

    cudaFuncSetAttribute(attn_kernel, cudaFuncAttributeMaxDynamicSharedMemorySize, SMEM_BYTES);

    // QKV projections
    gemm_nt_kernel<<<dim3(Ee / 128, MS / 128), 256>>>(x, Wq, qb, Ee, Ee);
    gemm_nt_kernel<<<dim3((HKVv * Dd) / 128, MS / 128), 256>>>(x, Wk, kb, Ee, HKVv * Dd);
    gemm_nt_kernel<<<dim3((HKVv * Dd) / 128, MS / 128), 256>>>(x, Wv, vb, Ee, HKVv * Dd);

    // RoPE in-place on q, k
    int total_pairs = MS * Hh * 32 + MS * HKVv * 32;
    rope_kernel<<<(total_pairs + 255) / 256, 256>>>(qb, kb, cosb, sinb);

    // Flash attention
    attn_kernel<<<dim3(Ss / QT, Hh, Bb), 128, SMEM_BYTES>>>(qb, kb, vb, ab);

    // Output projection
    gemm_nt_kernel<<<dim3(Ee / 128, MS / 128), 256>>>(ab, Wo, out, Ee, Ee);
}

// round 3
// speedup vs baseline: 1.3153x; 1.3153x over previous
#include <cuda_runtime.h>
#include <cstdint>
#include <math.h>

// Problem constants
constexpr int Bb  = 2;
constexpr int Ss  = 2048;
constexpr int Ee  = 2048;
constexpr int Hh  = 32;
constexpr int HKVv= 8;
constexpr int Dd  = 64;
constexpr int MS  = Bb * Ss;      // 4096 rows

// Scratch (no cudaMalloc allowed)
__device__ float g_q[MS * Hh * Dd];
__device__ float g_k[MS * HKVv * Dd];
__device__ float g_v[MS * HKVv * Dd];
__device__ float g_attn[MS * Hh * Dd];

// ---------------------------------------------------------------------------
// Warp-MMA helpers (sm_80+ instructions only — valid on base compute_103)
// ---------------------------------------------------------------------------
__device__ __forceinline__ uint32_t smem_u32(const void* p) {
    uint32_t a;
    asm("{ .reg .u64 t; cvta.to.shared.u64 t, %1; cvt.u32.u64 %0, t; }" : "=r"(a) : "l"(p));
    return a;
}

#define LDX4(r0, r1, r2, r3, addr) \
    asm volatile("ldmatrix.sync.aligned.m8n8.x4.shared.b16 {%0,%1,%2,%3}, [%4];" \
        : "=r"(r0), "=r"(r1), "=r"(r2), "=r"(r3) : "r"(addr))

__device__ __forceinline__ void mma_bf16(float c[4], const uint32_t a[4], const uint32_t b[2]) {
    asm volatile("mma.sync.aligned.m16n8k16.row.col.f32.bf16.bf16.f32 "
                 "{%0,%1,%2,%3}, {%4,%5,%6,%7}, {%8,%9}, {%0,%1,%2,%3};"
                 : "+f"(c[0]), "+f"(c[1]), "+f"(c[2]), "+f"(c[3])
                 : "r"(a[0]), "r"(a[1]), "r"(a[2]), "r"(a[3]), "r"(b[0]), "r"(b[1]));
}

// pack the high 16 bits of two floats (truncation split): {bf16(x0), bf16(x1)}
__device__ __forceinline__ uint32_t hi2(float x0, float x1) {
    return __byte_perm(__float_as_uint(x0), __float_as_uint(x1), 0x7632);
}
// residual lo parts rounded to bf16x2 (low half = lo of x0)
__device__ __forceinline__ uint32_t lo2(float x0, float x1) {
    float h0 = __uint_as_float(__float_as_uint(x0) & 0xFFFF0000u);
    float h1 = __uint_as_float(__float_as_uint(x1) & 0xFFFF0000u);
    float l0 = x0 - h0, l1 = x1 - h1;
    uint32_t r;
    asm("cvt.rn.bf16x2.f32 %0, %1, %2;" : "=r"(r) : "f"(l1), "f"(l0));
    return r;
}

// ---------------------------------------------------------------------------
// bf16-split NT GEMM: C[M,N] = A[M,K] * W[N,K]^T, fp32-accurate (~1e-5).
// Block 128x128, BK=16, 256 threads (8 warps x 64x32 warp tiles).
// Smem rows: 16 bf16 = 32B + 16B pad = 48B (ldmatrix conflict-free).
// ---------------------------------------------------------------------------
constexpr int G_ROWB  = 48;                 // bytes per smem row
constexpr int G_TILE  = 128 * G_ROWB;       // 6144 B
constexpr int G_AHI = 0;
constexpr int G_ALO = G_TILE;
constexpr int G_BHI = 2 * G_TILE;
constexpr int G_BLO = 3 * G_TILE;
constexpr int G_STAGE = 4 * G_TILE;         // 24576 B
constexpr int G_SMEM  = 2 * G_STAGE;        // 49152 B

__global__ void __launch_bounds__(256, 2) gemm_mma_kernel(
    const float* __restrict__ A, const float* __restrict__ W,
    float* __restrict__ C, int K, int ldc)
{
    extern __shared__ char smem[];
    const uint32_t sbase = smem_u32(smem);
    const int tid  = threadIdx.x;
    const int wid  = tid >> 5;
    const int lane = tid & 31;
    const int m0 = blockIdx.y * 128;
    const int n0 = blockIdx.x * 128;
    const int wm = wid & 1;        // 2 m-tiles of 64
    const int wn = wid >> 1;       // 4 n-tiles of 32

    // per-thread loader coords: one 8-float chunk for A and B each
    const int lrow8 = tid >> 1;          // 0..127
    const int lc    = (tid & 1) * 8;     // 0 or 8 (float offset)
    const uint32_t sts_off = (uint32_t)lrow8 * G_ROWB + (tid & 1) * 16;

    // ldmatrix lane mapping: mat = lane>>3
    const int lmrow = (lane & 7) + ((lane >> 3) & 1) * 8;  // row within 16
    const int lmk   = (lane >> 4) * 16;                    // byte offset for k8-15 mats

    float acc[4][4][4];
#pragma unroll
    for (int i = 0; i < 4; ++i)
#pragma unroll
        for (int j = 0; j < 4; ++j)
#pragma unroll
            for (int r = 0; r < 4; ++r) acc[i][j][r] = 0.f;

    const float* Ap = A + (size_t)(m0 + lrow8) * K + lc;
    const float* Wp = W + (size_t)(n0 + lrow8) * K + lc;

    auto load_stage = [&](int kt, int s) {
        const float* ap = Ap + kt * 16;
        const float* wp = Wp + kt * 16;
        float4 a0 = *(const float4*)(ap);
        float4 a1 = *(const float4*)(ap + 4);
        float4 b0 = *(const float4*)(wp);
        float4 b1 = *(const float4*)(wp + 4);
        char* st = smem + s * G_STAGE;
        uint4 h, l;
        h.x = hi2(a0.x, a0.y); h.y = hi2(a0.z, a0.w);
        h.z = hi2(a1.x, a1.y); h.w = hi2(a1.z, a1.w);
        l.x = lo2(a0.x, a0.y); l.y = lo2(a0.z, a0.w);
        l.z = lo2(a1.x, a1.y); l.w = lo2(a1.z, a1.w);
        *(uint4*)(st + G_AHI + sts_off) = h;
        *(uint4*)(st + G_ALO + sts_off) = l;
        h.x = hi2(b0.x, b0.y); h.y = hi2(b0.z, b0.w);
        h.z = hi2(b1.x, b1.y); h.w = hi2(b1.z, b1.w);
        l.x = lo2(b0.x, b0.y); l.y = lo2(b0.z, b0.w);
        l.z = lo2(b1.x, b1.y); l.w = lo2(b1.z, b1.w);
        *(uint4*)(st + G_BHI + sts_off) = h;
        *(uint4*)(st + G_BLO + sts_off) = l;
    };

    load_stage(0, 0);
    __syncthreads();

    const int NT = K >> 4;
    for (int kt = 0; kt < NT; ++kt) {
        const int buf = kt & 1;
        const uint32_t tb = sbase + buf * G_STAGE;

        // prefetch next tile (LDG issued early; convert+STS after MMA section)
        float4 a0, a1, b0, b1;
        const bool more = (kt + 1 < NT);
        if (more) {
            const float* ap = Ap + (kt + 1) * 16;
            const float* wp = Wp + (kt + 1) * 16;
            a0 = *(const float4*)(ap);
            a1 = *(const float4*)(ap + 4);
            b0 = *(const float4*)(wp);
            b1 = *(const float4*)(wp + 4);
        }

        // ---- MMA section on buf ----
        uint32_t bh[4][2], bl[4][2];
#pragma unroll
        for (int g = 0; g < 2; ++g) {
            uint32_t r0, r1, r2, r3;
            uint32_t baddr = tb + G_BHI + (uint32_t)(wn * 32 + g * 16 + lmrow) * G_ROWB + lmk;
            LDX4(r0, r1, r2, r3, baddr);
            bh[g * 2][0] = r0; bh[g * 2][1] = r2;
            bh[g * 2 + 1][0] = r1; bh[g * 2 + 1][1] = r3;
            uint32_t baddr2 = tb + G_BLO + (uint32_t)(wn * 32 + g * 16 + lmrow) * G_ROWB + lmk;
            LDX4(r0, r1, r2, r3, baddr2);
            bl[g * 2][0] = r0; bl[g * 2][1] = r2;
            bl[g * 2 + 1][0] = r1; bl[g * 2 + 1][1] = r3;
        }
        uint32_t af[4][4];
#pragma unroll
        for (int mt = 0; mt < 4; ++mt) {
            uint32_t aaddr = tb + G_AHI + (uint32_t)(wm * 64 + mt * 16 + lmrow) * G_ROWB + lmk;
            LDX4(af[mt][0], af[mt][1], af[mt][2], af[mt][3], aaddr);
        }
#pragma unroll
        for (int mt = 0; mt < 4; ++mt)
#pragma unroll
            for (int nt = 0; nt < 4; ++nt) {
                mma_bf16(acc[mt][nt], af[mt], bh[nt]);
                mma_bf16(acc[mt][nt], af[mt], bl[nt]);
            }
#pragma unroll
        for (int mt = 0; mt < 4; ++mt) {
            uint32_t aaddr = tb + G_ALO + (uint32_t)(wm * 64 + mt * 16 + lmrow) * G_ROWB + lmk;
            LDX4(af[mt][0], af[mt][1], af[mt][2], af[mt][3], aaddr);
        }
#pragma unroll
        for (int mt = 0; mt < 4; ++mt)
#pragma unroll
            for (int nt = 0; nt < 4; ++nt)
                mma_bf16(acc[mt][nt], af[mt], bh[nt]);

        // ---- convert + STS next stage ----
        if (more) {
            char* st = smem + (buf ^ 1) * G_STAGE;
            uint4 h, l;
            h.x = hi2(a0.x, a0.y); h.y = hi2(a0.z, a0.w);
            h.z = hi2(a1.x, a1.y); h.w = hi2(a1.z, a1.w);
            l.x = lo2(a0.x, a0.y); l.y = lo2(a0.z, a0.w);
            l.z = lo2(a1.x, a1.y); l.w = lo2(a1.z, a1.w);
            *(uint4*)(st + G_AHI + sts_off) = h;
            *(uint4*)(st + G_ALO + sts_off) = l;
            h.x = hi2(b0.x, b0.y); h.y = hi2(b0.z, b0.w);
            h.z = hi2(b1.x, b1.y); h.w = hi2(b1.z, b1.w);
            l.x = lo2(b0.x, b0.y); l.y = lo2(b0.z, b0.w);
            l.z = lo2(b1.x, b1.y); l.w = lo2(b1.z, b1.w);
            *(uint4*)(st + G_BHI + sts_off) = h;
            *(uint4*)(st + G_BLO + sts_off) = l;
        }
        __syncthreads();
    }

    // epilogue: direct STG of c fragments
    const int g = lane >> 2;
    const int t = lane & 3;
#pragma unroll
    for (int mt = 0; mt < 4; ++mt) {
#pragma unroll
        for (int nt = 0; nt < 4; ++nt) {
            int r = m0 + wm * 64 + mt * 16 + g;
            int c = n0 + wn * 32 + nt * 8 + t * 2;
            *(float2*)(C + (size_t)r * ldc + c)       = make_float2(acc[mt][nt][0], acc[mt][nt][1]);
            *(float2*)(C + (size_t)(r + 8) * ldc + c) = make_float2(acc[mt][nt][2], acc[mt][nt][3]);
        }
    }
}

// ---------------------------------------------------------------------------
// RoPE applied in-place to q (B,S,H,D) and k (B,S,HKV,D)
// ---------------------------------------------------------------------------
__global__ void rope_kernel(float* __restrict__ q, float* __restrict__ k,
                            const float* __restrict__ cosb, const float* __restrict__ sinb)
{
    const int NQ = MS * Hh * 32;
    const int NK = MS * HKVv * 32;
    int idx = blockIdx.x * blockDim.x + threadIdx.x;
    if (idx < NQ) {
        int d = idx & 31;
        int t = idx >> 5;
        int bs = t / Hh;
        int s = bs & (Ss - 1);
        float c1 = cosb[s * Dd + d],      s1 = sinb[s * Dd + d];
        float c2 = cosb[s * Dd + d + 32], s2 = sinb[s * Dd + d + 32];
        float* p = q + (size_t)t * Dd;
        float x1 = p[d], x2 = p[d + 32];
        p[d]      = x1 * c1 - x2 * s1;
        p[d + 32] = x2 * c2 + x1 * s2;
    } else if (idx < NQ + NK) {
        int j = idx - NQ;
        int d = j & 31;
        int t = j >> 5;
        int bs = t / HKVv;
        int s = bs & (Ss - 1);
        float c1 = cosb[s * Dd + d],      s1 = sinb[s * Dd + d];
        float c2 = cosb[s * Dd + d + 32], s2 = sinb[s * Dd + d + 32];
        float* p = k + (size_t)t * Dd;
        float x1 = p[d], x2 = p[d + 32];
        p[d]      = x1 * c1 - x2 * s1;
        p[d + 32] = x2 * c2 + x1 * s2;
    }
}

// ---------------------------------------------------------------------------
// Flash attention, fp32 FFMA (unchanged). Q tile 128, KV tile 64, 128 thr.
// ---------------------------------------------------------------------------
constexpr int QT   = 128;
constexpr int KT   = 64;
constexpr int QT_P = QT + 4;
constexpr int KT_P = KT + 4;

constexpr int OFF_QT = 0;
constexpr int OFF_KT = OFF_QT + 64 * QT_P;
constexpr int OFF_VS = OFF_KT + 64 * KT_P;
constexpr int OFF_PT = OFF_VS + KT * 64;
constexpr int SMEM_FLOATS = OFF_PT + KT * QT_P;
constexpr int A_SMEM_BYTES = SMEM_FLOATS * 4;

__global__ void __launch_bounds__(128, 2) attn_kernel(
    const float* __restrict__ q, const float* __restrict__ k,
    const float* __restrict__ v, float* __restrict__ o_out)
{
    extern __shared__ float sm[];
    float* Qt = sm + OFF_QT;
    float* Kt = sm + OFF_KT;
    float* Vs = sm + OFF_VS;
    float* Pt = sm + OFF_PT;

    const int tid = threadIdx.x;
    const int tn  = tid & 7;
    const int tm  = tid >> 3;
    const int q0  = blockIdx.x * QT;
    const int h   = blockIdx.y;
    const int b   = blockIdx.z;
    const int hkv = h >> 2;

    const float* qbase = q + ((size_t)(b * Ss) * Hh + h) * Dd;
    const float* kbase = k + ((size_t)(b * Ss) * HKVv + hkv) * Dd;
    const float* vbase = v + ((size_t)(b * Ss) * HKVv + hkv) * Dd;

#pragma unroll
    for (int r = 0; r < 16; ++r) {
        int idx = r * 128 + tid;
        int m  = idx >> 4;
        int d4 = (idx & 15) << 2;
        float4 val = *(const float4*)(qbase + (size_t)(q0 + m) * (Hh * Dd) + d4);
        Qt[(d4 + 0) * QT_P + m] = val.x;
        Qt[(d4 + 1) * QT_P + m] = val.y;
        Qt[(d4 + 2) * QT_P + m] = val.z;
        Qt[(d4 + 3) * QT_P + m] = val.w;
    }

    float o[8][8];
#pragma unroll
    for (int i = 0; i < 8; ++i)
#pragma unroll
        for (int j = 0; j < 8; ++j) o[i][j] = 0.f;
    float mstat[8], lstat[8];
#pragma unroll
    for (int i = 0; i < 8; ++i) { mstat[i] = -1e30f; lstat[i] = 0.f; }

    __syncthreads();

    for (int t = 0; t < Ss / KT; ++t) {
        const int kv0 = t * KT;
#pragma unroll
        for (int r = 0; r < 8; ++r) {
            int idx = r * 128 + tid;
            int pos = idx >> 4;
            int d4  = (idx & 15) << 2;
            float4 kval = *(const float4*)(kbase + (size_t)(kv0 + pos) * (HKVv * Dd) + d4);
            Kt[(d4 + 0) * KT_P + pos] = kval.x;
            Kt[(d4 + 1) * KT_P + pos] = kval.y;
            Kt[(d4 + 2) * KT_P + pos] = kval.z;
            Kt[(d4 + 3) * KT_P + pos] = kval.w;
            float4 vval = *(const float4*)(vbase + (size_t)(kv0 + pos) * (HKVv * Dd) + d4);
            *(float4*)(Vs + pos * 64 + d4) = vval;
        }
        __syncthreads();

        float s[8][8];
#pragma unroll
        for (int i = 0; i < 8; ++i)
#pragma unroll
            for (int j = 0; j < 8; ++j) s[i][j] = 0.f;

#pragma unroll 8
        for (int d = 0; d < 64; ++d) {
            float4 q0v = *(const float4*)(Qt + d * QT_P + 4 * tm);
            float4 q1v = *(const float4*)(Qt + d * QT_P + 64 + 4 * tm);
            float4 k0v = *(const float4*)(Kt + d * KT_P + 4 * tn);
            float4 k1v = *(const float4*)(Kt + d * KT_P + 32 + 4 * tn);
            float qa[8] = {q0v.x, q0v.y, q0v.z, q0v.w, q1v.x, q1v.y, q1v.z, q1v.w};
            float ka[8] = {k0v.x, k0v.y, k0v.z, k0v.w, k1v.x, k1v.y, k1v.z, k1v.w};
#pragma unroll
            for (int i = 0; i < 8; ++i)
#pragma unroll
                for (int j = 0; j < 8; ++j)
                    s[i][j] += qa[i] * ka[j];
        }

#pragma unroll
        for (int i = 0; i < 8; ++i) {
#pragma unroll
            for (int j = 0; j < 8; ++j) s[i][j] *= 0.125f;
            float rmax = s[i][0];
#pragma unroll
            for (int j = 1; j < 8; ++j) rmax = fmaxf(rmax, s[i][j]);
            rmax = fmaxf(rmax, __shfl_xor_sync(0xffffffffu, rmax, 1));
            rmax = fmaxf(rmax, __shfl_xor_sync(0xffffffffu, rmax, 2));
            rmax = fmaxf(rmax, __shfl_xor_sync(0xffffffffu, rmax, 4));
            float mnew = fmaxf(mstat[i], rmax);
            float corr = __expf(mstat[i] - mnew);
            float rsum = 0.f;
#pragma unroll
            for (int j = 0; j < 8; ++j) {
                s[i][j] = __expf(s[i][j] - mnew);
                rsum += s[i][j];
            }
            rsum += __shfl_xor_sync(0xffffffffu, rsum, 1);
            rsum += __shfl_xor_sync(0xffffffffu, rsum, 2);
            rsum += __shfl_xor_sync(0xffffffffu, rsum, 4);
            lstat[i] = lstat[i] * corr + rsum;
            mstat[i] = mnew;
#pragma unroll
            for (int j = 0; j < 8; ++j) o[i][j] *= corr;
        }

#pragma unroll
        for (int j = 0; j < 8; ++j) {
            int ncol = (j < 4) ? (4 * tn + j) : (32 + 4 * tn + (j - 4));
            *(float4*)(Pt + ncol * QT_P + 4 * tm)      = make_float4(s[0][j], s[1][j], s[2][j], s[3][j]);
            *(float4*)(Pt + ncol * QT_P + 64 + 4 * tm) = make_float4(s[4][j], s[5][j], s[6][j], s[7][j]);
        }
        __syncthreads();

#pragma unroll 8
        for (int kv = 0; kv < KT; ++kv) {
            float4 p0 = *(const float4*)(Pt + kv * QT_P + 4 * tm);
            float4 p1 = *(const float4*)(Pt + kv * QT_P + 64 + 4 * tm);
            float4 v0 = *(const float4*)(Vs + kv * 64 + 4 * tn);
            float4 v1 = *(const float4*)(Vs + kv * 64 + 32 + 4 * tn);
            float pa[8] = {p0.x, p0.y, p0.z, p0.w, p1.x, p1.y, p1.z, p1.w};
            float va[8] = {v0.x, v0.y, v0.z, v0.w, v1.x, v1.y, v1.z, v1.w};
#pragma unroll
            for (int i = 0; i < 8; ++i)
#pragma unroll
                for (int j = 0; j < 8; ++j)
                    o[i][j] += pa[i] * va[j];
        }
        __syncthreads();
    }

    float* obase = o_out + ((size_t)(b * Ss) * Hh + h) * Dd;
#pragma unroll
    for (int i = 0; i < 8; ++i) {
        int m = (i < 4) ? (4 * tm + i) : (64 + 4 * tm + (i - 4));
        float inv = 1.f / lstat[i];
        float* op = obase + (size_t)(q0 + m) * (Hh * Dd);
        *(float4*)(op + 4 * tn)      = make_float4(o[i][0] * inv, o[i][1] * inv, o[i][2] * inv, o[i][3] * inv);
        *(float4*)(op + 32 + 4 * tn) = make_float4(o[i][4] * inv, o[i][5] * inv, o[i][6] * inv, o[i][7] * inv);
    }
}

// ---------------------------------------------------------------------------
extern "C" void kernel_launch(void* const* d_in, const int* in_sizes, int n_in,
                              void* d_out, int out_size)
{
    (void)in_sizes; (void)n_in; (void)out_size;
    const float* x    = (const float*)d_in[0];
    const float* cosb = (const float*)d_in[1];
    const float* sinb = (const float*)d_in[2];
    const float* Wq   = (const float*)d_in[3];
    const float* Wk   = (const float*)d_in[4];
    const float* Wv   = (const float*)d_in[5];
    const float* Wo   = (const float*)d_in[6];
    float* out = (float*)d_out;

    float *qb, *kb, *vb, *ab;
    cudaGetSymbolAddress((void**)&qb, g_q);
    cudaGetSymbolAddress((void**)&kb, g_k);
    cudaGetSymbolAddress((void**)&vb, g_v);
    cudaGetSymbolAddress((void**)&ab, g_attn);

    cudaFuncSetAttribute(gemm_mma_kernel, cudaFuncAttributeMaxDynamicSharedMemorySize, G_SMEM);
    cudaFuncSetAttribute(attn_kernel, cudaFuncAttributeMaxDynamicSharedMemorySize, A_SMEM_BYTES);

    // QKV projections (bf16 split tensor-core GEMM)
    gemm_mma_kernel<<<dim3(Ee / 128, MS / 128), 256, G_SMEM>>>(x, Wq, qb, Ee, Ee);
    gemm_mma_kernel<<<dim3((HKVv * Dd) / 128, MS / 128), 256, G_SMEM>>>(x, Wk, kb, Ee, HKVv * Dd);
    gemm_mma_kernel<<<dim3((HKVv * Dd) / 128, MS / 128), 256, G_SMEM>>>(x, Wv, vb, Ee, HKVv * Dd);

    // RoPE in-place on q, k
    int total_pairs = MS * Hh * 32 + MS * HKVv * 32;
    rope_kernel<<<(total_pairs + 255) / 256, 256>>>(qb, kb, cosb, sinb);

    // Flash attention (fp32 FFMA — mma port is next)
    attn_kernel<<<dim3(Ss / QT, Hh, Bb), 128, A_SMEM_BYTES>>>(qb, kb, vb, ab);

    // Output projection
    gemm_mma_kernel<<<dim3(Ee / 128, MS / 128), 256, G_SMEM>>>(ab, Wo, out, Ee, Ee);
}

// round 4
// speedup vs baseline: 2.2887x; 1.7401x over previous
#include <cuda_runtime.h>
#include <cstdint>
#include <math.h>

// Problem constants
constexpr int Bb  = 2;
constexpr int Ss  = 2048;
constexpr int Ee  = 2048;
constexpr int Hh  = 32;
constexpr int HKVv= 8;
constexpr int Dd  = 64;
constexpr int MS  = Bb * Ss;      // 4096 rows

// Scratch (no cudaMalloc allowed)
__device__ float g_q[MS * Hh * Dd];
__device__ float g_k[MS * HKVv * Dd];
__device__ float g_v[MS * HKVv * Dd];
__device__ float g_attn[MS * Hh * Dd];

// ---------------------------------------------------------------------------
// Warp-MMA helpers (sm_80+ instructions only — valid on base compute_103)
// ---------------------------------------------------------------------------
__device__ __forceinline__ uint32_t smem_u32(const void* p) {
    uint32_t a;
    asm("{ .reg .u64 t; cvta.to.shared.u64 t, %1; cvt.u32.u64 %0, t; }" : "=r"(a) : "l"(p));
    return a;
}

#define LDX4(r0, r1, r2, r3, addr) \
    asm volatile("ldmatrix.sync.aligned.m8n8.x4.shared.b16 {%0,%1,%2,%3}, [%4];" \
        : "=r"(r0), "=r"(r1), "=r"(r2), "=r"(r3) : "r"(addr))

#define LDX4T(r0, r1, r2, r3, addr) \
    asm volatile("ldmatrix.sync.aligned.m8n8.x4.trans.shared.b16 {%0,%1,%2,%3}, [%4];" \
        : "=r"(r0), "=r"(r1), "=r"(r2), "=r"(r3) : "r"(addr))

__device__ __forceinline__ void mma_bf16(float c[4], const uint32_t a[4], const uint32_t b[2]) {
    asm volatile("mma.sync.aligned.m16n8k16.row.col.f32.bf16.bf16.f32 "
                 "{%0,%1,%2,%3}, {%4,%5,%6,%7}, {%8,%9}, {%0,%1,%2,%3};"
                 : "+f"(c[0]), "+f"(c[1]), "+f"(c[2]), "+f"(c[3])
                 : "r"(a[0]), "r"(a[1]), "r"(a[2]), "r"(a[3]), "r"(b[0]), "r"(b[1]));
}

// pack the high 16 bits of two floats (truncation split): low half = bf16(x0)
__device__ __forceinline__ uint32_t hi2(float x0, float x1) {
    return __byte_perm(__float_as_uint(x0), __float_as_uint(x1), 0x7632);
}
// residual lo parts rounded to bf16x2 (low half = lo of x0)
__device__ __forceinline__ uint32_t lo2(float x0, float x1) {
    float h0 = __uint_as_float(__float_as_uint(x0) & 0xFFFF0000u);
    float h1 = __uint_as_float(__float_as_uint(x1) & 0xFFFF0000u);
    float l0 = x0 - h0, l1 = x1 - h1;
    uint32_t r;
    asm("cvt.rn.bf16x2.f32 %0, %1, %2;" : "=r"(r) : "f"(l1), "f"(l0));
    return r;
}
// rne pack: {bf16(x1) : bf16(x0)}
__device__ __forceinline__ uint32_t packf(float x0, float x1) {
    uint32_t r;
    asm("cvt.rn.bf16x2.f32 %0, %1, %2;" : "=r"(r) : "f"(x1), "f"(x0));
    return r;
}
// residual pack given rne-pack ph of (x0,x1)
__device__ __forceinline__ uint32_t packlo(uint32_t ph, float x0, float x1) {
    float r0 = x0 - __uint_as_float(ph << 16);
    float r1 = x1 - __uint_as_float(ph & 0xFFFF0000u);
    return packf(r0, r1);
}

// ---------------------------------------------------------------------------
// bf16-split NT GEMM: C[M,N] = A[M,K] * W[N,K]^T (unchanged from R3)
// ---------------------------------------------------------------------------
constexpr int G_ROWB  = 48;
constexpr int G_TILE  = 128 * G_ROWB;
constexpr int G_AHI = 0;
constexpr int G_ALO = G_TILE;
constexpr int G_BHI = 2 * G_TILE;
constexpr int G_BLO = 3 * G_TILE;
constexpr int G_STAGE = 4 * G_TILE;
constexpr int G_SMEM  = 2 * G_STAGE;

__global__ void __launch_bounds__(256, 2) gemm_mma_kernel(
    const float* __restrict__ A, const float* __restrict__ W,
    float* __restrict__ C, int K, int ldc)
{
    extern __shared__ char smem[];
    const uint32_t sbase = smem_u32(smem);
    const int tid  = threadIdx.x;
    const int wid  = tid >> 5;
    const int lane = tid & 31;
    const int m0 = blockIdx.y * 128;
    const int n0 = blockIdx.x * 128;
    const int wm = wid & 1;
    const int wn = wid >> 1;

    const int lrow8 = tid >> 1;
    const int lc    = (tid & 1) * 8;
    const uint32_t sts_off = (uint32_t)lrow8 * G_ROWB + (tid & 1) * 16;

    const int lmrow = (lane & 7) + ((lane >> 3) & 1) * 8;
    const int lmk   = (lane >> 4) * 16;

    float acc[4][4][4];
#pragma unroll
    for (int i = 0; i < 4; ++i)
#pragma unroll
        for (int j = 0; j < 4; ++j)
#pragma unroll
            for (int r = 0; r < 4; ++r) acc[i][j][r] = 0.f;

    const float* Ap = A + (size_t)(m0 + lrow8) * K + lc;
    const float* Wp = W + (size_t)(n0 + lrow8) * K + lc;

    auto load_stage = [&](int kt, int s) {
        const float* ap = Ap + kt * 16;
        const float* wp = Wp + kt * 16;
        float4 a0 = *(const float4*)(ap);
        float4 a1 = *(const float4*)(ap + 4);
        float4 b0 = *(const float4*)(wp);
        float4 b1 = *(const float4*)(wp + 4);
        char* st = smem + s * G_STAGE;
        uint4 h, l;
        h.x = hi2(a0.x, a0.y); h.y = hi2(a0.z, a0.w);
        h.z = hi2(a1.x, a1.y); h.w = hi2(a1.z, a1.w);
        l.x = lo2(a0.x, a0.y); l.y = lo2(a0.z, a0.w);
        l.z = lo2(a1.x, a1.y); l.w = lo2(a1.z, a1.w);
        *(uint4*)(st + G_AHI + sts_off) = h;
        *(uint4*)(st + G_ALO + sts_off) = l;
        h.x = hi2(b0.x, b0.y); h.y = hi2(b0.z, b0.w);
        h.z = hi2(b1.x, b1.y); h.w = hi2(b1.z, b1.w);
        l.x = lo2(b0.x, b0.y); l.y = lo2(b0.z, b0.w);
        l.z = lo2(b1.x, b1.y); l.w = lo2(b1.z, b1.w);
        *(uint4*)(st + G_BHI + sts_off) = h;
        *(uint4*)(st + G_BLO + sts_off) = l;
    };

    load_stage(0, 0);
    __syncthreads();

    const int NT = K >> 4;
    for (int kt = 0; kt < NT; ++kt) {
        const int buf = kt & 1;
        const uint32_t tb = sbase + buf * G_STAGE;

        float4 a0, a1, b0, b1;
        const bool more = (kt + 1 < NT);
        if (more) {
            const float* ap = Ap + (kt + 1) * 16;
            const float* wp = Wp + (kt + 1) * 16;
            a0 = *(const float4*)(ap);
            a1 = *(const float4*)(ap + 4);
            b0 = *(const float4*)(wp);
            b1 = *(const float4*)(wp + 4);
        }

        uint32_t bh[4][2], bl[4][2];
#pragma unroll
        for (int g = 0; g < 2; ++g) {
            uint32_t r0, r1, r2, r3;
            uint32_t baddr = tb + G_BHI + (uint32_t)(wn * 32 + g * 16 + lmrow) * G_ROWB + lmk;
            LDX4(r0, r1, r2, r3, baddr);
            bh[g * 2][0] = r0; bh[g * 2][1] = r2;
            bh[g * 2 + 1][0] = r1; bh[g * 2 + 1][1] = r3;
            uint32_t baddr2 = tb + G_BLO + (uint32_t)(wn * 32 + g * 16 + lmrow) * G_ROWB + lmk;
            LDX4(r0, r1, r2, r3, baddr2);
            bl[g * 2][0] = r0; bl[g * 2][1] = r2;
            bl[g * 2 + 1][0] = r1; bl[g * 2 + 1][1] = r3;
        }
        uint32_t af[4][4];
#pragma unroll
        for (int mt = 0; mt < 4; ++mt) {
            uint32_t aaddr = tb + G_AHI + (uint32_t)(wm * 64 + mt * 16 + lmrow) * G_ROWB + lmk;
            LDX4(af[mt][0], af[mt][1], af[mt][2], af[mt][3], aaddr);
        }
#pragma unroll
        for (int mt = 0; mt < 4; ++mt)
#pragma unroll
            for (int nt = 0; nt < 4; ++nt) {
                mma_bf16(acc[mt][nt], af[mt], bh[nt]);
                mma_bf16(acc[mt][nt], af[mt], bl[nt]);
            }
#pragma unroll
        for (int mt = 0; mt < 4; ++mt) {
            uint32_t aaddr = tb + G_ALO + (uint32_t)(wm * 64 + mt * 16 + lmrow) * G_ROWB + lmk;
            LDX4(af[mt][0], af[mt][1], af[mt][2], af[mt][3], aaddr);
        }
#pragma unroll
        for (int mt = 0; mt < 4; ++mt)
#pragma unroll
            for (int nt = 0; nt < 4; ++nt)
                mma_bf16(acc[mt][nt], af[mt], bh[nt]);

        if (more) {
            char* st = smem + (buf ^ 1) * G_STAGE;
            uint4 h, l;
            h.x = hi2(a0.x, a0.y); h.y = hi2(a0.z, a0.w);
            h.z = hi2(a1.x, a1.y); h.w = hi2(a1.z, a1.w);
            l.x = lo2(a0.x, a0.y); l.y = lo2(a0.z, a0.w);
            l.z = lo2(a1.x, a1.y); l.w = lo2(a1.z, a1.w);
            *(uint4*)(st + G_AHI + sts_off) = h;
            *(uint4*)(st + G_ALO + sts_off) = l;
            h.x = hi2(b0.x, b0.y); h.y = hi2(b0.z, b0.w);
            h.z = hi2(b1.x, b1.y); h.w = hi2(b1.z, b1.w);
            l.x = lo2(b0.x, b0.y); l.y = lo2(b0.z, b0.w);
            l.z = lo2(b1.x, b1.y); l.w = lo2(b1.z, b1.w);
            *(uint4*)(st + G_BHI + sts_off) = h;
            *(uint4*)(st + G_BLO + sts_off) = l;
        }
        __syncthreads();
    }

    const int g = lane >> 2;
    const int t = lane & 3;
#pragma unroll
    for (int mt = 0; mt < 4; ++mt) {
#pragma unroll
        for (int nt = 0; nt < 4; ++nt) {
            int r = m0 + wm * 64 + mt * 16 + g;
            int c = n0 + wn * 32 + nt * 8 + t * 2;
            *(float2*)(C + (size_t)r * ldc + c)       = make_float2(acc[mt][nt][0], acc[mt][nt][1]);
            *(float2*)(C + (size_t)(r + 8) * ldc + c) = make_float2(acc[mt][nt][2], acc[mt][nt][3]);
        }
    }
}

// ---------------------------------------------------------------------------
// RoPE applied in-place to q (B,S,H,D) and k (B,S,HKV,D)
// ---------------------------------------------------------------------------
__global__ void rope_kernel(float* __restrict__ q, float* __restrict__ k,
                            const float* __restrict__ cosb, const float* __restrict__ sinb)
{
    const int NQ = MS * Hh * 32;
    const int NK = MS * HKVv * 32;
    int idx = blockIdx.x * blockDim.x + threadIdx.x;
    if (idx < NQ) {
        int d = idx & 31;
        int t = idx >> 5;
        int bs = t / Hh;
        int s = bs & (Ss - 1);
        float c1 = cosb[s * Dd + d],      s1 = sinb[s * Dd + d];
        float c2 = cosb[s * Dd + d + 32], s2 = sinb[s * Dd + d + 32];
        float* p = q + (size_t)t * Dd;
        float x1 = p[d], x2 = p[d + 32];
        p[d]      = x1 * c1 - x2 * s1;
        p[d + 32] = x2 * c2 + x1 * s2;
    } else if (idx < NQ + NK) {
        int j = idx - NQ;
        int d = j & 31;
        int t = j >> 5;
        int bs = t / HKVv;
        int s = bs & (Ss - 1);
        float c1 = cosb[s * Dd + d],      s1 = sinb[s * Dd + d];
        float c2 = cosb[s * Dd + d + 32], s2 = sinb[s * Dd + d + 32];
        float* p = k + (size_t)t * Dd;
        float x1 = p[d], x2 = p[d + 32];
        p[d]      = x1 * c1 - x2 * s1;
        p[d + 32] = x2 * c2 + x1 * s2;
    }
}

// ---------------------------------------------------------------------------
// Flash attention on mma.sync bf16 with hi/lo split.
// Block: 256 thr (8 warps), Q tile 128 (16 rows/warp), KV tile 64.
// smem rows 144B (9 x 16B -> ldmatrix conflict-free).
// ---------------------------------------------------------------------------
constexpr int AROW = 144;
constexpr int A_QH = 0;
constexpr int A_QL = A_QH + 128 * AROW;
constexpr int A_KH = A_QL + 128 * AROW;
constexpr int A_KL = A_KH + 64 * AROW;
constexpr int A_VH = A_KL + 64 * AROW;
constexpr int A_VL = A_VH + 64 * AROW;
constexpr int A_SMEM = A_VL + 64 * AROW;   // 73728 B

__global__ void __launch_bounds__(256, 1) attn_mma_kernel(
    const float* __restrict__ q, const float* __restrict__ k,
    const float* __restrict__ v, float* __restrict__ o_out)
{
    extern __shared__ char sm[];
    const uint32_t sb = smem_u32(sm);
    const int tid  = threadIdx.x;
    const int wid  = tid >> 5;
    const int lane = tid & 31;
    const int q0 = blockIdx.x * 128;
    const int h  = blockIdx.y;
    const int b  = blockIdx.z;
    const int hkv = h >> 2;

    const float* qbase = q + (size_t)(b * Ss) * 2048 + h * 64;
    const float* kbase = k + (size_t)(b * Ss) * 512 + hkv * 64;
    const float* vbase = v + (size_t)(b * Ss) * 512 + hkv * 64;

    const int lmrow = (lane & 7) + ((lane >> 3) & 1) * 8;
    const int lmk   = (lane >> 4) * 16;
    const int arow16 = lane & 15;

    // ---- load Q tile -> QH/QL ----
#pragma unroll
    for (int r = 0; r < 8; ++r) {
        int idx = r * 256 + tid;
        int row = idx >> 4;
        int c4  = (idx & 15) * 4;
        float4 val = *(const float4*)(qbase + (size_t)(q0 + row) * 2048 + c4);
        *(uint2*)(sm + A_QH + row * AROW + c4 * 2) =
            make_uint2(hi2(val.x, val.y), hi2(val.z, val.w));
        *(uint2*)(sm + A_QL + row * AROW + c4 * 2) =
            make_uint2(lo2(val.x, val.y), lo2(val.z, val.w));
    }

    float o[8][4];
#pragma unroll
    for (int j = 0; j < 8; ++j)
#pragma unroll
        for (int r = 0; r < 4; ++r) o[j][r] = 0.f;
    float mstat[2] = {-1e30f, -1e30f};
    float lstat[2] = {0.f, 0.f};

    float4 kreg[4], vreg[4];
    // tile 0 global load
#pragma unroll
    for (int i = 0; i < 4; ++i) {
        int idx = i * 256 + tid;
        int row = idx >> 4;
        int c4  = (idx & 15) * 4;
        kreg[i] = *(const float4*)(kbase + (size_t)row * 512 + c4);
        vreg[i] = *(const float4*)(vbase + (size_t)row * 512 + c4);
    }
    // STS tile 0
#pragma unroll
    for (int i = 0; i < 4; ++i) {
        int idx = i * 256 + tid;
        int row = idx >> 4;
        int cb  = (idx & 15) * 8;
        *(uint2*)(sm + A_KH + row * AROW + cb) = make_uint2(hi2(kreg[i].x, kreg[i].y), hi2(kreg[i].z, kreg[i].w));
        *(uint2*)(sm + A_KL + row * AROW + cb) = make_uint2(lo2(kreg[i].x, kreg[i].y), lo2(kreg[i].z, kreg[i].w));
        *(uint2*)(sm + A_VH + row * AROW + cb) = make_uint2(hi2(vreg[i].x, vreg[i].y), hi2(vreg[i].z, vreg[i].w));
        *(uint2*)(sm + A_VL + row * AROW + cb) = make_uint2(lo2(vreg[i].x, vreg[i].y), lo2(vreg[i].z, vreg[i].w));
    }
    __syncthreads();

    for (int t = 0; t < Ss / 64; ++t) {
        const bool more = (t + 1 < Ss / 64);
        // prefetch next KV tile into registers
        if (more) {
            const float* kp = kbase + (size_t)(t + 1) * 64 * 512;
            const float* vp = vbase + (size_t)(t + 1) * 64 * 512;
#pragma unroll
            for (int i = 0; i < 4; ++i) {
                int idx = i * 256 + tid;
                int row = idx >> 4;
                int c4  = (idx & 15) * 4;
                kreg[i] = *(const float4*)(kp + (size_t)row * 512 + c4);
                vreg[i] = *(const float4*)(vp + (size_t)row * 512 + c4);
            }
        }

        // ---- S = Q K^T (3-term split) ----
        float s[8][4];
#pragma unroll
        for (int j = 0; j < 8; ++j)
#pragma unroll
            for (int r = 0; r < 4; ++r) s[j][r] = 0.f;

#pragma unroll
        for (int kd = 0; kd < 4; ++kd) {
            uint32_t ah[4], al[4];
            LDX4(ah[0], ah[1], ah[2], ah[3],
                 sb + A_QH + (uint32_t)(wid * 16 + arow16) * AROW + kd * 32 + lmk);
            LDX4(al[0], al[1], al[2], al[3],
                 sb + A_QL + (uint32_t)(wid * 16 + arow16) * AROW + kd * 32 + lmk);
#pragma unroll
            for (int j16 = 0; j16 < 4; ++j16) {
                uint32_t h0, h1, h2, h3, l0, l1, l2, l3;
                LDX4(h0, h1, h2, h3,
                     sb + A_KH + (uint32_t)(j16 * 16 + lmrow) * AROW + kd * 32 + lmk);
                LDX4(l0, l1, l2, l3,
                     sb + A_KL + (uint32_t)(j16 * 16 + lmrow) * AROW + kd * 32 + lmk);
                uint32_t bh0[2] = {h0, h2}, bh1[2] = {h1, h3};
                uint32_t bl0[2] = {l0, l2}, bl1[2] = {l1, l3};
                mma_bf16(s[2 * j16],     ah, bh0);
                mma_bf16(s[2 * j16],     ah, bl0);
                mma_bf16(s[2 * j16],     al, bh0);
                mma_bf16(s[2 * j16 + 1], ah, bh1);
                mma_bf16(s[2 * j16 + 1], ah, bl1);
                mma_bf16(s[2 * j16 + 1], al, bh1);
            }
        }

        // ---- online softmax ----
#pragma unroll
        for (int hf = 0; hf < 2; ++hf) {
            float mx = -1e30f;
#pragma unroll
            for (int j = 0; j < 8; ++j) {
                s[j][hf * 2]     *= 0.125f;
                s[j][hf * 2 + 1] *= 0.125f;
                mx = fmaxf(mx, fmaxf(s[j][hf * 2], s[j][hf * 2 + 1]));
            }
            mx = fmaxf(mx, __shfl_xor_sync(0xffffffffu, mx, 1));
            mx = fmaxf(mx, __shfl_xor_sync(0xffffffffu, mx, 2));
            float mnew = fmaxf(mstat[hf], mx);
            float corr = __expf(mstat[hf] - mnew);
            float sum = 0.f;
#pragma unroll
            for (int j = 0; j < 8; ++j) {
                s[j][hf * 2]     = __expf(s[j][hf * 2] - mnew);
                s[j][hf * 2 + 1] = __expf(s[j][hf * 2 + 1] - mnew);
                sum += s[j][hf * 2] + s[j][hf * 2 + 1];
            }
            sum += __shfl_xor_sync(0xffffffffu, sum, 1);
            sum += __shfl_xor_sync(0xffffffffu, sum, 2);
            lstat[hf] = lstat[hf] * corr + sum;
            mstat[hf] = mnew;
#pragma unroll
            for (int j = 0; j < 8; ++j) {
                o[j][hf * 2]     *= corr;
                o[j][hf * 2 + 1] *= corr;
            }
        }

        // ---- O += P V (3-term split; P packed from registers) ----
#pragma unroll
        for (int kk = 0; kk < 4; ++kk) {
            uint32_t ah[4], al[4];
            ah[0] = packf(s[2 * kk][0],     s[2 * kk][1]);
            ah[1] = packf(s[2 * kk][2],     s[2 * kk][3]);
            ah[2] = packf(s[2 * kk + 1][0], s[2 * kk + 1][1]);
            ah[3] = packf(s[2 * kk + 1][2], s[2 * kk + 1][3]);
            al[0] = packlo(ah[0], s[2 * kk][0],     s[2 * kk][1]);
            al[1] = packlo(ah[1], s[2 * kk][2],     s[2 * kk][3]);
            al[2] = packlo(ah[2], s[2 * kk + 1][0], s[2 * kk + 1][1]);
            al[3] = packlo(ah[3], s[2 * kk + 1][2], s[2 * kk + 1][3]);
#pragma unroll
            for (int j = 0; j < 4; ++j) {
                uint32_t vh0, vh1, vh2, vh3, vl0, vl1, vl2, vl3;
                LDX4T(vh0, vh1, vh2, vh3,
                      sb + A_VH + (uint32_t)(kk * 16 + lmrow) * AROW + j * 32 + lmk);
                LDX4T(vl0, vl1, vl2, vl3,
                      sb + A_VL + (uint32_t)(kk * 16 + lmrow) * AROW + j * 32 + lmk);
                uint32_t bh0[2] = {vh0, vh1}, bh1[2] = {vh2, vh3};
                uint32_t bl0[2] = {vl0, vl1}, bl1[2] = {vl2, vl3};
                mma_bf16(o[2 * j],     ah, bh0);
                mma_bf16(o[2 * j],     al, bh0);
                mma_bf16(o[2 * j],     ah, bl0);
                mma_bf16(o[2 * j + 1], ah, bh1);
                mma_bf16(o[2 * j + 1], al, bh1);
                mma_bf16(o[2 * j + 1], ah, bl1);
            }
        }

        // ---- stage next tile ----
        if (more) {
            __syncthreads();
#pragma unroll
            for (int i = 0; i < 4; ++i) {
                int idx = i * 256 + tid;
                int row = idx >> 4;
                int cb  = (idx & 15) * 8;
                *(uint2*)(sm + A_KH + row * AROW + cb) = make_uint2(hi2(kreg[i].x, kreg[i].y), hi2(kreg[i].z, kreg[i].w));
                *(uint2*)(sm + A_KL + row * AROW + cb) = make_uint2(lo2(kreg[i].x, kreg[i].y), lo2(kreg[i].z, kreg[i].w));
                *(uint2*)(sm + A_VH + row * AROW + cb) = make_uint2(hi2(vreg[i].x, vreg[i].y), hi2(vreg[i].z, vreg[i].w));
                *(uint2*)(sm + A_VL + row * AROW + cb) = make_uint2(lo2(vreg[i].x, vreg[i].y), lo2(vreg[i].z, vreg[i].w));
            }
            __syncthreads();
        }
    }

    // ---- epilogue ----
    const int g  = lane >> 2;
    const int tt = lane & 3;
    const float inv0 = 1.f / lstat[0];
    const float inv1 = 1.f / lstat[1];
    const int mrow = q0 + wid * 16 + g;
    float* ob = o_out + (size_t)(b * Ss + mrow) * 2048 + h * 64;
#pragma unroll
    for (int j = 0; j < 8; ++j) {
        *(float2*)(ob + j * 8 + tt * 2) =
            make_float2(o[j][0] * inv0, o[j][1] * inv0);
        *(float2*)(ob + (size_t)8 * 2048 + j * 8 + tt * 2) =
            make_float2(o[j][2] * inv1, o[j][3] * inv1);
    }
}

// ---------------------------------------------------------------------------
extern "C" void kernel_launch(void* const* d_in, const int* in_sizes, int n_in,
                              void* d_out, int out_size)
{
    (void)in_sizes; (void)n_in; (void)out_size;
    const float* x    = (const float*)d_in[0];
    const float* cosb = (const float*)d_in[1];
    const float* sinb = (const float*)d_in[2];
    const float* Wq   = (const float*)d_in[3];
    const float* Wk   = (const float*)d_in[4];
    const float* Wv   = (const float*)d_in[5];
    const float* Wo   = (const float*)d_in[6];
    float* out = (float*)d_out;

    float *qb, *kb, *vb, *ab;
    cudaGetSymbolAddress((void**)&qb, g_q);
    cudaGetSymbolAddress((void**)&kb, g_k);
    cudaGetSymbolAddress((void**)&vb, g_v);
    cudaGetSymbolAddress((void**)&ab, g_attn);

    cudaFuncSetAttribute(gemm_mma_kernel, cudaFuncAttributeMaxDynamicSharedMemorySize, G_SMEM);
    cudaFuncSetAttribute(attn_mma_kernel, cudaFuncAttributeMaxDynamicSharedMemorySize, A_SMEM);

    // QKV projections (bf16 split tensor-core GEMM)
    gemm_mma_kernel<<<dim3(Ee / 128, MS / 128), 256, G_SMEM>>>(x, Wq, qb, Ee, Ee);
    gemm_mma_kernel<<<dim3((HKVv * Dd) / 128, MS / 128), 256, G_SMEM>>>(x, Wk, kb, Ee, HKVv * Dd);
    gemm_mma_kernel<<<dim3((HKVv * Dd) / 128, MS / 128), 256, G_SMEM>>>(x, Wv, vb, Ee, HKVv * Dd);

    // RoPE in-place on q, k
    int total_pairs = MS * Hh * 32 + MS * HKVv * 32;
    rope_kernel<<<(total_pairs + 255) / 256, 256>>>(qb, kb, cosb, sinb);

    // Flash attention (bf16 split mma.sync)
    attn_mma_kernel<<<dim3(Ss / 128, Hh, Bb), 256, A_SMEM>>>(qb, kb, vb, ab);

    // Output projection
    gemm_mma_kernel<<<dim3(Ee / 128, MS / 128), 256, G_SMEM>>>(ab, Wo, out, Ee, Ee);
}